// round 2
// baseline (speedup 1.0000x reference)
#include <cuda_runtime.h>
#include <cstdint>

#define NB      256   // batch
#define DIN     256   // input channels
#define DH      512   // hidden channels
#define WDIM    8
#define PIX     64    // 8x8
#define CB      32    // hidden channels per block
#define ROWS    128   // 4 gates * CB
#define CIC     8     // input-channel chunk staged in smem
#define THREADS 256

typedef unsigned long long ull;

// ---- packed f32x2 helpers (Blackwell sm_103a) ----
__device__ __forceinline__ ull pk(float lo, float hi) {
    ull r; asm("mov.b64 %0, {%1, %2};" : "=l"(r) : "f"(lo), "f"(hi)); return r;
}
__device__ __forceinline__ void fma2(ull& d, ull a, ull b) {
    asm("fma.rn.f32x2 %0, %1, %2, %0;" : "+l"(d) : "l"(a), "l"(b));
}
__device__ __forceinline__ float2 upk(ull v) {
    float2 r; asm("mov.b64 {%0, %1}, %2;" : "=f"(r.x), "=f"(r.y) : "l"(v)); return r;
}

// One 3x3 reflect-padded conv accumulated into acc[4 rows][4 pixel-pairs].
// Rows r0..r0+3 index into the 128-row (4 gates x 32 ch) output tile.
__device__ __forceinline__ void conv_pass(
    const float* __restrict__ src,          // [CIN, 8, 8] for this image
    const float* w0, const float* w1, const float* w2, const float* w3,
    int CIN, int c_base, int t, int pg, int r0,
    ull acc[4][4], float* s_in, float* s_w)
{
    const float* wptr[4] = {w0, w1, w2, w3};
    for (int cib = 0; cib < CIN; cib += CIC) {
        __syncthreads();
        // Stage input tile with reflect padding: CIC x 10 x 10
        for (int i = t; i < CIC * 100; i += THREADS) {
            int ci = i / 100; int p = i - ci * 100;
            int yy = p / 10;  int xx = p - yy * 10;
            int ry = (yy == 0) ? 1 : ((yy == 9) ? 6 : yy - 1);
            int rx = (xx == 0) ? 1 : ((xx == 9) ? 6 : xx - 1);
            s_in[i] = src[(size_t)(cib + ci) * PIX + ry * WDIM + rx];
        }
        // Stage weights: ROWS x CIC x 9 floats (float2 vectorized, aligned)
        for (int i = t; i < ROWS * (CIC * 9 / 2); i += THREADS) {
            int r = i / 36; int rem = i - r * 36;
            int g = r >> 5; int c = c_base + (r & 31);
            const float2* wsrc = reinterpret_cast<const float2*>(
                wptr[g] + ((size_t)c * CIN + cib) * 9);
            reinterpret_cast<float2*>(s_w)[i] = wsrc[rem];
        }
        __syncthreads();

        for (int ci = 0; ci < CIC; ci++) {
            // Load the 3 padded input rows this thread's output row needs,
            // as even pairs E[k]=(v[2k],v[2k+1]) and odd pairs O[k]=(v[2k+1],v[2k+2]).
            ull E[3][5], O[3][4];
            #pragma unroll
            for (int dy = 0; dy < 3; dy++) {
                const float2* rp = reinterpret_cast<const float2*>(
                    &s_in[ci * 100 + (pg + dy) * 10]);
                float2 e0 = rp[0], e1 = rp[1], e2 = rp[2], e3 = rp[3], e4 = rp[4];
                E[dy][0] = pk(e0.x, e0.y);
                E[dy][1] = pk(e1.x, e1.y);
                E[dy][2] = pk(e2.x, e2.y);
                E[dy][3] = pk(e3.x, e3.y);
                E[dy][4] = pk(e4.x, e4.y);
                O[dy][0] = pk(e0.y, e1.x);
                O[dy][1] = pk(e1.y, e2.x);
                O[dy][2] = pk(e2.y, e3.x);
                O[dy][3] = pk(e3.y, e4.x);
            }
            #pragma unroll
            for (int r = 0; r < 4; r++) {
                const float* wr = &s_w[(r0 + r) * (CIC * 9) + ci * 9];
                #pragma unroll
                for (int dy = 0; dy < 3; dy++) {
                    ull wA = pk(wr[dy * 3 + 0], wr[dy * 3 + 0]);
                    ull wB = pk(wr[dy * 3 + 1], wr[dy * 3 + 1]);
                    ull wC = pk(wr[dy * 3 + 2], wr[dy * 3 + 2]);
                    // out[x pair p] covers px (2p, 2p+1):
                    //  dx=0 -> E[p], dx=1 -> O[p], dx=2 -> E[p+1]
                    #pragma unroll
                    for (int p = 0; p < 4; p++) {
                        fma2(acc[r][p], wA, E[dy][p]);
                        fma2(acc[r][p], wB, O[dy][p]);
                        fma2(acc[r][p], wC, E[dy][p + 1]);
                    }
                }
            }
        }
    }
}

__global__ void __launch_bounds__(THREADS, 2) convlstm_kernel(
    const float* __restrict__ x,   const float* __restrict__ hs,
    const float* __restrict__ wii, const float* __restrict__ wif_,
    const float* __restrict__ wig, const float* __restrict__ wio,
    const float* __restrict__ whi, const float* __restrict__ whf,
    const float* __restrict__ whg, const float* __restrict__ who,
    const float* __restrict__ bi,  const float* __restrict__ bf,
    const float* __restrict__ bg,  const float* __restrict__ bo,
    const float* __restrict__ wci, const float* __restrict__ wcf,
    const float* __restrict__ wco,
    float* __restrict__ out)
{
    // Union: during conv loop [s_in (800) | s_w (9216)]; afterwards s_pre (8192).
    __shared__ float smem[10048];
    float* s_in  = smem;
    float* s_w   = smem + CIC * 100;
    float* s_pre = smem;

    const int t  = threadIdx.x;
    const int pg = t & 7;          // output row y (0..7)
    const int r0 = (t >> 3) * 4;   // first of 4 gate-rows this thread owns
    const int n  = blockIdx.y;
    const int c_base = blockIdx.x * CB;

    ull acc[4][4] = {};  // 4 rows x 4 pixel-pairs, packed fp32 pairs (zero = 0.0f,0.0f)

    // pre = conv(x_pad, w_x) + conv(h0_pad, w_h)
    conv_pass(x  + (size_t)n * DIN * PIX,       wii, wif_, wig, wio,
              DIN, c_base, t, pg, r0, acc, s_in, s_w);
    conv_pass(hs + (size_t)(n * 2) * DH * PIX,  whi, whf, whg, who,
              DH,  c_base, t, pg, r0, acc, s_in, s_w);

    __syncthreads();   // all reads of s_in/s_w done before aliasing as s_pre
    #pragma unroll
    for (int r = 0; r < 4; r++) {
        #pragma unroll
        for (int p = 0; p < 4; p++) {
            float2 v = upk(acc[r][p]);
            s_pre[(r0 + r) * PIX + pg * 8 + 2 * p]     = v.x;
            s_pre[(r0 + r) * PIX + pg * 8 + 2 * p + 1] = v.y;
        }
    }
    __syncthreads();

    // Gate math + outputs. Rows: gate g channel cl lives at row g*32+cl.
    const float* c0p = hs + ((size_t)(n * 2) + 1) * DH * PIX;
    const size_t base2 = (size_t)NB * DH * PIX;   // start of hidden_state_out
    for (int e = t; e < CB * PIX; e += THREADS) {
        int cl = e >> 6; int px = e & 63;
        int c = c_base + cl;
        float pi  = s_pre[(cl)      * PIX + px] + bi[c];
        float pf  = s_pre[(32 + cl) * PIX + px] + bf[c];
        float pgv = s_pre[(64 + cl) * PIX + px] + bg[c];
        float po  = s_pre[(96 + cl) * PIX + px] + bo[c];

        float c0 = c0p[(size_t)c * PIX + px];
        float vi = wci[c * PIX + px];
        float vf = wcf[c * PIX + px];
        float vo = wco[c * PIX + px];

        float ig = 1.f / (1.f + expf(-(pi + c0 * vi)));
        float fg = 1.f / (1.f + expf(-(pf + c0 * vf)));
        float gg = tanhf(pgv);
        float ct = fg * c0 + ig * gg;
        float og = 1.f / (1.f + expf(-(po + ct * vo)));
        float ht = og * tanhf(ct);

        out[((size_t)n * DH + c) * PIX + px] = og;                              // o
        out[base2 + (((size_t)n * 2) * DH + c) * PIX + px]     = ht;            // h_t
        out[base2 + (((size_t)n * 2 + 1) * DH + c) * PIX + px] = ct;            // c_t
    }
}

extern "C" void kernel_launch(void* const* d_in, const int* in_sizes, int n_in,
                              void* d_out, int out_size) {
    (void)in_sizes; (void)n_in; (void)out_size;
    const float* x    = (const float*)d_in[0];
    const float* hs   = (const float*)d_in[1];
    const float* wii  = (const float*)d_in[2];
    const float* wif_ = (const float*)d_in[3];
    const float* wig  = (const float*)d_in[4];
    const float* wio  = (const float*)d_in[5];
    const float* whi  = (const float*)d_in[6];
    const float* whf  = (const float*)d_in[7];
    const float* whg  = (const float*)d_in[8];
    const float* who  = (const float*)d_in[9];
    const float* bi   = (const float*)d_in[10];
    const float* bf   = (const float*)d_in[11];
    const float* bg   = (const float*)d_in[12];
    const float* bo   = (const float*)d_in[13];
    const float* wci  = (const float*)d_in[14];
    const float* wcf  = (const float*)d_in[15];
    const float* wco  = (const float*)d_in[16];

    dim3 grid(DH / CB, NB);   // 16 channel-chunks x 256 images
    convlstm_kernel<<<grid, THREADS>>>(
        x, hs, wii, wif_, wig, wio, whi, whf, whg, who,
        bi, bf, bg, bo, wci, wcf, wco, (float*)d_out);
}